// round 1
// baseline (speedup 1.0000x reference)
#include <cuda_runtime.h>

static constexpr int E    = 128;
static constexpr int BATCH = 512;
static constexpr int NTOT = 1365;

// hsum scratch offsets (floats). Level-d kernel reads S_d, writes S_{d-1}.
static constexpr long OFF_S4 = 0;                         // 512*256*128 (written by d=5)
static constexpr long OFF_S3 = OFF_S4 + 512L * 256 * 128; // 512*64*128
static constexpr long OFF_S2 = OFF_S3 + 512L * 64 * 128;  // 512*16*128
static constexpr long OFF_S1 = OFF_S2 + 512L * 16 * 128;  // 512*4*128
static constexpr long OFF_S0 = OFF_S1 + 512L * 4 * 128;   // 512*1*128
static constexpr long SCRATCH_TOTAL = OFF_S0 + 512L * 1 * 128;

__device__ float g_scratch[SCRATCH_TOTAL];
__device__ float g_WcT[E * E];
__device__ float g_WsT[E * E];

// Pre-transpose weights to k-major so level kernels load/stage them with zero
// shared-memory bank conflicts (warp reads/writes contiguous 512B rows).
__global__ void transpose_w_kernel(const float* __restrict__ Wc,
                                   const float* __restrict__ Ws) {
    int idx = blockIdx.x * blockDim.x + threadIdx.x;
    if (idx < E * E) {
        int c = idx >> 7;
        int k = idx & 127;
        g_WcT[k * E + c] = Wc[idx];
        g_WsT[k * E + c] = Ws[idx];
    }
}

// One kernel per tree level. Block = 256 threads computes a 64-row x 128-col
// tile of h for this level:
//   h[row] = emb[token[row]] @ Wc^T + Wc_b  (+ hsum_in[row] @ Ws^T + 4*Ws_b)
// Epilogue: ReLU-max folded into out via atomicMax (float bits of non-negative
// floats are monotone as ints), and sums of 4 consecutive sibling rows written
// to hsum_out (each thread owns 8 consecutive rows = 2 full sibling groups).
template <bool HAS_CHILD, bool WRITE_HSUM, bool BLOCK_MAX>
__global__ __launch_bounds__(256)
void level_kernel(const int*   __restrict__ tokens,
                  const float* __restrict__ emb,
                  const float* __restrict__ Wcb,
                  const float* __restrict__ Wsb,
                  const float* __restrict__ hsum_in,
                  float*       __restrict__ hsum_out,
                  float*       __restrict__ out,
                  int L, int tok_start) {
    extern __shared__ float smem[];
    float* sWc  = smem;                                   // 16384 f, k-major WcT
    float* sWs  = sWc + 16384;                            // 16384 f if HAS_CHILD
    float* sX   = sWs + (HAS_CHILD ? 16384 : 0);          // 64x128 gathered emb
    float* sS   = sX + 64 * E;                            // 64x128 child sums
    float* sRed = sS + (HAS_CHILD ? 64 * E : 0);          // 8x128 max-reduce
    int*   sTok = (int*)(sRed + 8 * E);                   // 64 tokens

    const int tid = threadIdx.x;
    const int rg  = tid >> 5;        // row group 0..7 (warp id)
    const int cg  = tid & 31;        // col group 0..31
    const int c0  = cg * 4;
    const int rowBase = blockIdx.x * 64;

    // Stage tokens for this tile.
    if (tid < 64) {
        int gr = rowBase + tid;
        int b  = gr / L;
        int i  = gr - b * L;
        sTok[tid] = tokens[b * NTOT + tok_start + i];
    }
    // Stage weights (already k-major in global; fully coalesced, conflict-free).
    {
        const float4* src = (const float4*)g_WcT;
        float4*       dst = (float4*)sWc;
        for (int i = tid; i < E * E / 4; i += 256) dst[i] = src[i];
        if (HAS_CHILD) {
            const float4* s2 = (const float4*)g_WsT;
            float4*       d2 = (float4*)sWs;
            for (int i = tid; i < E * E / 4; i += 256) d2[i] = s2[i];
        }
    }
    __syncthreads();

    // Gather 64 embedding rows; warp handles one row (contiguous 512B).
#pragma unroll
    for (int it = 0; it < 8; ++it) {
        int flat = it * 256 + tid;
        int row  = flat >> 5;
        int k4   = flat & 31;
        float4 v = *(const float4*)&emb[(long)sTok[row] * E + k4 * 4];
        *(float4*)&sX[row * E + k4 * 4] = v;
    }
    if (HAS_CHILD) {
#pragma unroll
        for (int it = 0; it < 8; ++it) {
            int flat = it * 256 + tid;
            int row  = flat >> 5;
            int k4   = flat & 31;
            *(float4*)&sS[row * E + k4 * 4] =
                *(const float4*)&hsum_in[(long)(rowBase + row) * E + k4 * 4];
        }
    }
    __syncthreads();

    // Accumulators: 8 rows x 4 cols per thread. Bias init (Ws_b counted A=4x).
    float acc[8][4];
    {
        float4 bc = *(const float4*)&Wcb[c0];
        float bx = bc.x, by = bc.y, bz = bc.z, bw = bc.w;
        if (HAS_CHILD) {
            float4 bs = *(const float4*)&Wsb[c0];
            bx += 4.f * bs.x; by += 4.f * bs.y; bz += 4.f * bs.z; bw += 4.f * bs.w;
        }
#pragma unroll
        for (int j = 0; j < 8; ++j) {
            acc[j][0] = bx; acc[j][1] = by; acc[j][2] = bz; acc[j][3] = bw;
        }
    }

    // Wc GEMM: per k, one conflict-free LDS.128 of WcT row + 8 broadcast LDS.32.
    {
        const float* xrow = &sX[rg * 8 * E];
#pragma unroll 4
        for (int k = 0; k < E; ++k) {
            float4 w = *(const float4*)&sWc[k * E + c0];
#pragma unroll
            for (int j = 0; j < 8; ++j) {
                float a = xrow[j * E + k];
                acc[j][0] += a * w.x; acc[j][1] += a * w.y;
                acc[j][2] += a * w.z; acc[j][3] += a * w.w;
            }
        }
    }
    if (HAS_CHILD) {
        const float* srow = &sS[rg * 8 * E];
#pragma unroll 4
        for (int k = 0; k < E; ++k) {
            float4 w = *(const float4*)&sWs[k * E + c0];
#pragma unroll
            for (int j = 0; j < 8; ++j) {
                float a = srow[j * E + k];
                acc[j][0] += a * w.x; acc[j][1] += a * w.y;
                acc[j][2] += a * w.z; acc[j][3] += a * w.w;
            }
        }
    }

    // Sibling sums: thread's 8 consecutive rows = 2 complete groups of 4.
    if (WRITE_HSUM) {
#pragma unroll
        for (int g = 0; g < 2; ++g) {
            float4 s;
            s.x = acc[g*4+0][0] + acc[g*4+1][0] + acc[g*4+2][0] + acc[g*4+3][0];
            s.y = acc[g*4+0][1] + acc[g*4+1][1] + acc[g*4+2][1] + acc[g*4+3][1];
            s.z = acc[g*4+0][2] + acc[g*4+1][2] + acc[g*4+2][2] + acc[g*4+3][2];
            s.w = acc[g*4+0][3] + acc[g*4+1][3] + acc[g*4+2][3] + acc[g*4+3][3];
            long prow = (long)(rowBase + rg * 8) / 4 + g;
            *(float4*)&hsum_out[prow * E + c0] = s;
        }
    }

    // ReLU + running max into out.
    if (BLOCK_MAX) {
        // L >= 64: whole tile is one batch element -> block-reduce, 128 atomics.
        float m0 = 0.f, m1 = 0.f, m2 = 0.f, m3 = 0.f;
#pragma unroll
        for (int j = 0; j < 8; ++j) {
            m0 = fmaxf(m0, acc[j][0]); m1 = fmaxf(m1, acc[j][1]);
            m2 = fmaxf(m2, acc[j][2]); m3 = fmaxf(m3, acc[j][3]);
        }
        float4 mv = make_float4(m0, m1, m2, m3);
        *(float4*)&sRed[rg * E + c0] = mv;
        __syncthreads();
        if (tid < E) {
            float mm = 0.f;
#pragma unroll
            for (int g = 0; g < 8; ++g) mm = fmaxf(mm, sRed[g * E + tid]);
            int b = rowBase / L;
            atomicMax((int*)&out[b * E + tid], __float_as_int(mm));
        }
    } else {
        // Small levels (tile spans batches): per-row atomics (cheap here).
#pragma unroll
        for (int j = 0; j < 8; ++j) {
            int gr = rowBase + rg * 8 + j;
            int b  = gr / L;
#pragma unroll
            for (int i = 0; i < 4; ++i) {
                float v = fmaxf(acc[j][i], 0.f);
                atomicMax((int*)&out[b * E + c0 + i], __float_as_int(v));
            }
        }
    }
}

static constexpr size_t SMEM_INTERNAL =
    (size_t)(16384 * 2 + 64 * E * 2 + 8 * E) * 4 + 64 * 4;
static constexpr size_t SMEM_LEAF =
    (size_t)(16384 + 64 * E + 8 * E) * 4 + 64 * 4;

extern "C" void kernel_launch(void* const* d_in, const int* in_sizes, int n_in,
                              void* d_out, int out_size) {
    const int*   tokens = (const int*)d_in[0];
    const float* emb    = (const float*)d_in[1];
    const float* WcW    = (const float*)d_in[2];
    const float* Wcb    = (const float*)d_in[3];
    const float* WsW    = (const float*)d_in[4];
    const float* Wsb    = (const float*)d_in[5];
    float*       out    = (float*)d_out;

    cudaFuncSetAttribute(level_kernel<false, true,  true >,
                         cudaFuncAttributeMaxDynamicSharedMemorySize, SMEM_LEAF);
    cudaFuncSetAttribute(level_kernel<true,  true,  true >,
                         cudaFuncAttributeMaxDynamicSharedMemorySize, SMEM_INTERNAL);
    cudaFuncSetAttribute(level_kernel<true,  true,  false>,
                         cudaFuncAttributeMaxDynamicSharedMemorySize, SMEM_INTERNAL);
    cudaFuncSetAttribute(level_kernel<true,  false, false>,
                         cudaFuncAttributeMaxDynamicSharedMemorySize, SMEM_INTERNAL);

    float* scratch = nullptr;
    cudaGetSymbolAddress((void**)&scratch, g_scratch);
    float* S4 = scratch + OFF_S4;
    float* S3 = scratch + OFF_S3;
    float* S2 = scratch + OFF_S2;
    float* S1 = scratch + OFF_S1;
    float* S0 = scratch + OFF_S0;

    cudaMemsetAsync(d_out, 0, (size_t)out_size * sizeof(float), 0);
    transpose_w_kernel<<<(E * E + 255) / 256, 256>>>(WcW, WsW);

    // d=5 (leaves): L=1024, tok_start=341, writes S4
    level_kernel<false, true, true><<<512 * 1024 / 64, 256, SMEM_LEAF>>>(
        tokens, emb, Wcb, Wsb, nullptr, S4, out, 1024, 341);
    // d=4: L=256, start=85, S4 -> S3
    level_kernel<true, true, true><<<512 * 256 / 64, 256, SMEM_INTERNAL>>>(
        tokens, emb, Wcb, Wsb, S4, S3, out, 256, 85);
    // d=3: L=64, start=21, S3 -> S2
    level_kernel<true, true, true><<<512 * 64 / 64, 256, SMEM_INTERNAL>>>(
        tokens, emb, Wcb, Wsb, S3, S2, out, 64, 21);
    // d=2: L=16, start=5, S2 -> S1 (tile spans batches -> per-row max)
    level_kernel<true, true, false><<<512 * 16 / 64, 256, SMEM_INTERNAL>>>(
        tokens, emb, Wcb, Wsb, S2, S1, out, 16, 5);
    // d=1: L=4, start=1, S1 -> S0
    level_kernel<true, true, false><<<512 * 4 / 64, 256, SMEM_INTERNAL>>>(
        tokens, emb, Wcb, Wsb, S1, S0, out, 4, 1);
    // d=0: L=1, start=0, reads S0, no hsum out
    level_kernel<true, false, false><<<512 / 64, 256, SMEM_INTERNAL>>>(
        tokens, emb, Wcb, Wsb, S0, nullptr, out, 1, 0);
}

// round 3
// speedup vs baseline: 2.3656x; 2.3656x over previous
#include <cuda_runtime.h>
#include <cstdint>

static constexpr int NTOT = 1365;

// hsum scratch (floats). Level-d kernel reads S_d, writes S_{d-1}.
static constexpr long OFF_S4 = 0;
static constexpr long OFF_S3 = OFF_S4 + 512L * 256 * 128;
static constexpr long OFF_S2 = OFF_S3 + 512L * 64 * 128;
static constexpr long OFF_S1 = OFF_S2 + 512L * 16 * 128;
static constexpr long OFF_S0 = OFF_S1 + 512L * 4 * 128;
static constexpr long SCRATCH_TOTAL = OFF_S0 + 512L * 1 * 128;
__device__ float g_scratch[SCRATCH_TOTAL];

__device__ __forceinline__ uint32_t f2tf32(float f) {
    uint32_t r;
    asm("cvt.rna.tf32.f32 %0, %1;" : "=r"(r) : "f"(f));
    return r;
}

__device__ __forceinline__ void mma_tf32(float (&d)[4],
                                         uint32_t a0, uint32_t a1, uint32_t a2, uint32_t a3,
                                         uint32_t b0, uint32_t b1) {
    asm volatile(
        "mma.sync.aligned.m16n8k8.row.col.f32.tf32.tf32.f32 "
        "{%0,%1,%2,%3}, {%4,%5,%6,%7}, {%8,%9}, {%0,%1,%2,%3};"
        : "+f"(d[0]), "+f"(d[1]), "+f"(d[2]), "+f"(d[3])
        : "r"(a0), "r"(a1), "r"(a2), "r"(a3), "r"(b0), "r"(b1));
}

// smem strides (in floats)
static constexpr int WST = 136;   // weight row stride (conflict-free LDS.64 B-frags)
static constexpr int XST = 132;   // activation row stride (conflict-free LDS.32 A-frags)

// Per tile (64 nodes x 128 ch): H = X@Wc^T + (S@Ws^T) + bias, bias = Wcb + 4*Wsb.
// Epilogue: hsum_out[parent] = sum of 4 sibling h rows (incl bias); relu-max -> out.
template <bool HAS_CHILD, bool WRITE_HSUM, bool BLOCK_MAX>
__global__ __launch_bounds__(256)
void enc_kernel(const int*   __restrict__ tokens,
                const float* __restrict__ emb,
                const float* __restrict__ WcW, const float* __restrict__ Wcb,
                const float* __restrict__ WsW, const float* __restrict__ Wsb,
                const float* __restrict__ hsum_in,
                float*       __restrict__ hsum_out,
                float*       __restrict__ out,
                int Lshift, int tok_start, int numTiles) {
    extern __shared__ float sm[];
    float* sWc   = sm;                                  // 128*136
    float* sWs   = sWc + 128 * WST;                     // 128*136 (if HAS_CHILD)
    float* sX    = HAS_CHILD ? sWs + 128 * WST : sWs;   // 64*132
    float* sS    = sX + 64 * XST;                       // 64*132 (if HAS_CHILD)
    float* sBias = HAS_CHILD ? sS + 64 * XST : sS;      // 128
    float* sRed  = sBias + 128;                         // 4*128
    int*   sTok  = (int*)(sRed + 512);                  // 64

    const int tid  = threadIdx.x;
    const int lane = tid & 31;
    const int wrp  = tid >> 5;
    const int g    = wrp & 3;        // node group (16 nodes)
    const int cg   = wrp >> 2;       // channel half (64 ch)
    const int g4   = lane >> 2;      // 0..7
    const int c4   = lane & 3;       // 0..3

    // Stage weights once per CTA, tf32-rounded, k-pair interleaved:
    // within each 8-k chunk, order is k0,k4,k1,k5,k2,k6,k3,k7 so the B fragment
    // {k, k+4} is one aligned LDS.64.
    for (int i = tid; i < 16384; i += 256) {
        int ch = i >> 7, k = i & 127;
        int d  = ch * WST + (k & ~7) + 2 * (k & 3) + ((k >> 2) & 1);
        sWc[d] = __uint_as_float(f2tf32(WcW[i]));
        if (HAS_CHILD) sWs[d] = __uint_as_float(f2tf32(WsW[i]));
    }
    if (tid < 128) sBias[tid] = Wcb[tid] + (HAS_CHILD ? 4.f * Wsb[tid] : 0.f);
    __syncthreads();

    float bias_r[8][2];
#pragma unroll
    for (int t = 0; t < 8; ++t)
#pragma unroll
        for (int j = 0; j < 2; ++j)
            bias_r[t][j] = sBias[cg * 64 + t * 8 + 2 * c4 + j];

    const uint32_t* Xu = (const uint32_t*)sX;
    const uint32_t* Su = (const uint32_t*)sS;
    const uint32_t* WcU = (const uint32_t*)sWc;
    const uint32_t* WsU = (const uint32_t*)sWs;
    const int xr0 = (g * 16 + g4) * XST + c4;
    const int wb0 = (cg * 64 + g4) * WST + 2 * c4;

    for (int tile = blockIdx.x; tile < numTiles; tile += gridDim.x) {
        const int rowBase = tile * 64;

        if (tid < 64) {
            int gr = rowBase + tid;
            int b  = gr >> Lshift;
            sTok[tid] = tokens[b * NTOT + tok_start + (gr - (b << Lshift))];
        }
        __syncthreads();

#pragma unroll
        for (int it = 0; it < 8; ++it) {
            int f = it * 256 + tid;
            int row = f >> 5, k4 = f & 31;
            float4 v = *(const float4*)&emb[(long)sTok[row] * 128 + k4 * 4];
            float4 t;
            t.x = __uint_as_float(f2tf32(v.x)); t.y = __uint_as_float(f2tf32(v.y));
            t.z = __uint_as_float(f2tf32(v.z)); t.w = __uint_as_float(f2tf32(v.w));
            *(float4*)&sX[row * XST + k4 * 4] = t;
        }
        if (HAS_CHILD) {
#pragma unroll
            for (int it = 0; it < 8; ++it) {
                int f = it * 256 + tid;
                int row = f >> 5, k4 = f & 31;
                float4 v = *(const float4*)&hsum_in[(long)(rowBase + row) * 128 + k4 * 4];
                float4 t;
                t.x = __uint_as_float(f2tf32(v.x)); t.y = __uint_as_float(f2tf32(v.y));
                t.z = __uint_as_float(f2tf32(v.z)); t.w = __uint_as_float(f2tf32(v.w));
                *(float4*)&sS[row * XST + k4 * 4] = t;
            }
        }
        __syncthreads();

        float acc[8][4];
#pragma unroll
        for (int t = 0; t < 8; ++t)
#pragma unroll
            for (int i = 0; i < 4; ++i) acc[t][i] = 0.f;

#pragma unroll 4
        for (int ks = 0; ks < 16; ++ks) {
            const int kk = ks * 8;
            uint32_t a0 = Xu[xr0 + kk];
            uint32_t a2 = Xu[xr0 + kk + 4];
            uint32_t a1 = Xu[xr0 + 8 * XST + kk];
            uint32_t a3 = Xu[xr0 + 8 * XST + kk + 4];
#pragma unroll
            for (int t = 0; t < 8; ++t) {
                uint2 bb = *(const uint2*)&WcU[wb0 + t * 8 * WST + kk];
                mma_tf32(acc[t], a0, a1, a2, a3, bb.x, bb.y);
            }
        }
        if (HAS_CHILD) {
#pragma unroll 4
            for (int ks = 0; ks < 16; ++ks) {
                const int kk = ks * 8;
                uint32_t a0 = Su[xr0 + kk];
                uint32_t a2 = Su[xr0 + kk + 4];
                uint32_t a1 = Su[xr0 + 8 * XST + kk];
                uint32_t a3 = Su[xr0 + 8 * XST + kk + 4];
#pragma unroll
                for (int t = 0; t < 8; ++t) {
                    uint2 bb = *(const uint2*)&WsU[wb0 + t * 8 * WST + kk];
                    mma_tf32(acc[t], a0, a1, a2, a3, bb.x, bb.y);
                }
            }
        }

        // Sibling sums (groups of 4 node rows). D rows = nodes: row = g4 (+8).
        // shfl_xor 4,8 sums rows over (row mod 4) quad; lane bit4 selects quad.
        if (WRITE_HSUM) {
            const bool writer = (lane & 12) == 0;       // lanes 0-3, 16-19
            const int bit4 = (lane >> 4) & 1;
#pragma unroll
            for (int half = 0; half < 2; ++half) {
#pragma unroll
                for (int t = 0; t < 8; ++t) {
#pragma unroll
                    for (int j = 0; j < 2; ++j) {
                        float v = acc[t][half * 2 + j];
                        v += __shfl_xor_sync(0xffffffffu, v, 4);
                        v += __shfl_xor_sync(0xffffffffu, v, 8);
                        if (writer) {
                            int prow = ((rowBase + g * 16) >> 2) + half * 2 + bit4;
                            int col  = cg * 64 + t * 8 + 2 * c4 + j;
                            hsum_out[(long)prow * 128 + col] = v + 4.f * bias_r[t][j];
                        }
                    }
                }
            }
        }

        if (BLOCK_MAX) {
            // Whole 64-row tile lies in one batch element (64 | L).
#pragma unroll
            for (int t = 0; t < 8; ++t) {
#pragma unroll
                for (int j = 0; j < 2; ++j) {
                    float m = fmaxf(acc[t][j], acc[t][j + 2]);
                    m = fmaxf(m, __shfl_xor_sync(0xffffffffu, m, 4));
                    m = fmaxf(m, __shfl_xor_sync(0xffffffffu, m, 8));
                    m = fmaxf(m, __shfl_xor_sync(0xffffffffu, m, 16));
                    if (lane < 4)
                        sRed[g * 128 + cg * 64 + t * 8 + 2 * c4 + j] = m + bias_r[t][j];
                }
            }
            __syncthreads();
            if (tid < 128) {
                float mm = fmaxf(fmaxf(sRed[tid], sRed[128 + tid]),
                                 fmaxf(sRed[256 + tid], sRed[384 + tid]));
                mm = fmaxf(mm, 0.f);
                int b = rowBase >> Lshift;
                atomicMax((int*)&out[(b << 7) + tid], __float_as_int(mm));
            }
        } else {
            // Small L: direct per-element relu + atomicMax.
#pragma unroll
            for (int t = 0; t < 8; ++t) {
#pragma unroll
                for (int i = 0; i < 4; ++i) {
                    int rl = g * 16 + g4 + 8 * (i >> 1);
                    int gr = rowBase + rl;
                    int b  = gr >> Lshift;
                    int col = cg * 64 + t * 8 + 2 * c4 + (i & 1);
                    float v = fmaxf(acc[t][i] + bias_r[t][i & 1], 0.f);
                    atomicMax((int*)&out[(b << 7) + col], __float_as_int(v));
                }
            }
        }
        __syncthreads();   // tile smem reuse
    }
}

static constexpr size_t SMEM_INT =
    (size_t)(128 * WST * 2 + 64 * XST * 2 + 128 + 512) * 4 + 64 * 4;
static constexpr size_t SMEM_LEAF =
    (size_t)(128 * WST + 64 * XST + 128 + 512) * 4 + 64 * 4;

extern "C" void kernel_launch(void* const* d_in, const int* in_sizes, int n_in,
                              void* d_out, int out_size) {
    const int*   tokens = (const int*)d_in[0];
    const float* emb    = (const float*)d_in[1];
    const float* WcW    = (const float*)d_in[2];
    const float* Wcb    = (const float*)d_in[3];
    const float* WsW    = (const float*)d_in[4];
    const float* Wsb    = (const float*)d_in[5];
    float*       out    = (float*)d_out;

    cudaFuncSetAttribute(enc_kernel<false, true,  true >,
                         cudaFuncAttributeMaxDynamicSharedMemorySize, SMEM_LEAF);
    cudaFuncSetAttribute(enc_kernel<true,  true,  true >,
                         cudaFuncAttributeMaxDynamicSharedMemorySize, SMEM_INT);
    cudaFuncSetAttribute(enc_kernel<true,  true,  false>,
                         cudaFuncAttributeMaxDynamicSharedMemorySize, SMEM_INT);
    cudaFuncSetAttribute(enc_kernel<true,  false, false>,
                         cudaFuncAttributeMaxDynamicSharedMemorySize, SMEM_INT);

    float* scratch = nullptr;
    cudaGetSymbolAddress((void**)&scratch, g_scratch);
    float* S4 = scratch + OFF_S4;
    float* S3 = scratch + OFF_S3;
    float* S2 = scratch + OFF_S2;
    float* S1 = scratch + OFF_S1;
    float* S0 = scratch + OFF_S0;

    cudaMemsetAsync(d_out, 0, (size_t)out_size * sizeof(float), 0);

    // d=5 leaves: 524288 rows -> 8192 tiles (2 CTAs/SM fits: ~104KB smem)
    enc_kernel<false, true, true><<<296, 256, SMEM_LEAF>>>(
        tokens, emb, WcW, Wcb, WsW, Wsb, nullptr, S4, out, 10, 341, 8192);
    // d=4: 131072 rows -> 2048 tiles
    enc_kernel<true, true, true><<<148, 256, SMEM_INT>>>(
        tokens, emb, WcW, Wcb, WsW, Wsb, S4, S3, out, 8, 85, 2048);
    // d=3: 32768 rows -> 512 tiles
    enc_kernel<true, true, true><<<148, 256, SMEM_INT>>>(
        tokens, emb, WcW, Wcb, WsW, Wsb, S3, S2, out, 6, 21, 512);
    // d=2: 8192 rows -> 128 tiles (L=16 < 64: small-L path)
    enc_kernel<true, true, false><<<128, 256, SMEM_INT>>>(
        tokens, emb, WcW, Wcb, WsW, Wsb, S2, S1, out, 4, 5, 128);
    // d=1: 2048 rows -> 32 tiles
    enc_kernel<true, true, false><<<32, 256, SMEM_INT>>>(
        tokens, emb, WcW, Wcb, WsW, Wsb, S1, S0, out, 2, 1, 32);
    // d=0: 512 rows -> 8 tiles, no hsum out
    enc_kernel<true, false, false><<<8, 256, SMEM_INT>>>(
        tokens, emb, WcW, Wcb, WsW, Wsb, S0, nullptr, out, 0, 0, 8);
}

// round 4
// speedup vs baseline: 2.8370x; 1.1993x over previous
#include <cuda_runtime.h>
#include <cstdint>

static constexpr int NTOT = 1365;

// hsum scratch (floats).
static constexpr long OFF_S4 = 0;                          // 131072 x 128 (d5 out)
static constexpr long OFF_S3 = OFF_S4 + 512L * 256 * 128;  // 32768 x 128 (d4 out)
static constexpr long OFF_S2 = OFF_S3 + 512L * 64 * 128;   // 8192 x 128 (d3 out)
static constexpr long SCRATCH_TOTAL = OFF_S2 + 512L * 16 * 128;
__device__ float g_scratch[SCRATCH_TOTAL];

__device__ __forceinline__ uint32_t f2tf32(float f) {
    uint32_t r;
    asm("cvt.rna.tf32.f32 %0, %1;" : "=r"(r) : "f"(f));
    return r;
}
__device__ __forceinline__ uint32_t cvtb(uint32_t bits) {  // raw fp32 bits -> tf32
    return f2tf32(__uint_as_float(bits));
}
__device__ __forceinline__ uint32_t smem_u32(const void* p) {
    uint32_t a;
    asm("{ .reg .u64 t; cvta.to.shared.u64 t, %1; cvt.u32.u64 %0, t; }" : "=r"(a) : "l"(p));
    return a;
}
__device__ __forceinline__ void cp16(uint32_t dst, const void* src) {
    asm volatile("cp.async.cg.shared.global [%0], [%1], 16;"
                 :: "r"(dst), "l"(__cvta_generic_to_global(src)));
}
__device__ __forceinline__ void cp_commit() {
    asm volatile("cp.async.commit_group;" ::: "memory");
}
__device__ __forceinline__ void cp_wait1() {
    asm volatile("cp.async.wait_group 1;" ::: "memory");
}

__device__ __forceinline__ void mma_tf32(float (&d)[4],
                                         uint32_t a0, uint32_t a1, uint32_t a2, uint32_t a3,
                                         uint32_t b0, uint32_t b1) {
    asm volatile(
        "mma.sync.aligned.m16n8k8.row.col.f32.tf32.tf32.f32 "
        "{%0,%1,%2,%3}, {%4,%5,%6,%7}, {%8,%9}, {%0,%1,%2,%3};"
        : "+f"(d[0]), "+f"(d[1]), "+f"(d[2]), "+f"(d[3])
        : "r"(a0), "r"(a1), "r"(a2), "r"(a3), "r"(b0), "r"(b1));
}

static constexpr int WST = 136;   // weight row stride (floats), k-pair interleaved
static constexpr int XST = 132;   // activation row stride (floats)
static constexpr int XBUF = 32 * XST;   // one 32-row activation buffer

// ───────── main level kernel: 32-row tiles, cp.async double-buffered ─────────
// Warps: g = wrp&1 (16-row half), cg = wrp>>1 (32-channel quarter).
template <bool HAS_CHILD>
__global__ __launch_bounds__(256)
void enc32(const int*   __restrict__ tokens,
           const float* __restrict__ emb,
           const float* __restrict__ WcW, const float* __restrict__ Wcb,
           const float* __restrict__ WsW, const float* __restrict__ Wsb,
           const float* __restrict__ hsum_in,
           float*       __restrict__ hsum_out,
           float*       __restrict__ out,
           int Lshift, int tok_start, int numTiles) {
    extern __shared__ float sm[];
    constexpr int OFF_WS   = 128 * WST;
    constexpr int OFF_X    = OFF_WS + (HAS_CHILD ? 128 * WST : 0);
    constexpr int OFF_S    = OFF_X + 2 * XBUF;
    constexpr int OFF_BIAS = OFF_S + (HAS_CHILD ? 2 * XBUF : 0);
    constexpr int OFF_RED  = OFF_BIAS + 128;
    constexpr int OFF_TOK  = OFF_RED + 256;

    float* sBias = sm + OFF_BIAS;
    float* sRed  = sm + OFF_RED;
    int*   sTok  = (int*)(sm + OFF_TOK);       // 2 x 32
    const uint32_t sb32 = smem_u32(sm);

    const int tid  = threadIdx.x;
    const int lane = tid & 31;
    const int wrp  = tid >> 5;
    const int g    = wrp & 1;
    const int cg   = wrp >> 1;
    const int g4   = lane >> 2;
    const int c4   = lane & 3;

    // Stage weights once per CTA (rna-converted), k-pair interleaved for LDS.64 B-frags.
    for (int i = tid; i < 16384; i += 256) {
        int ch = i >> 7, k = i & 127;
        int d  = ch * WST + (k & ~7) + 2 * (k & 3) + ((k >> 2) & 1);
        sm[d] = __uint_as_float(f2tf32(WcW[i]));
        if (HAS_CHILD) sm[OFF_WS + d] = __uint_as_float(f2tf32(WsW[i]));
    }
    if (tid < 128) sBias[tid] = Wcb[tid] + (HAS_CHILD ? 4.f * Wsb[tid] : 0.f);
    __syncthreads();

    float bias_r[4][2];
#pragma unroll
    for (int t = 0; t < 4; ++t)
#pragma unroll
        for (int j = 0; j < 2; ++j)
            bias_r[t][j] = sBias[cg * 32 + t * 8 + 2 * c4 + j];

    const uint32_t* WcU = (const uint32_t*)sm;
    const uint32_t* WsU = (const uint32_t*)(sm + OFF_WS);
    const int xr0 = (g * 16 + g4) * XST + c4;
    const int wb0 = (cg * 32 + g4) * WST + 2 * c4;
    const int grid = gridDim.x;

    // cp.async issue for tile tt into buffer bb (reads sTok[bb]).
    auto issue_tile = [&](int tt, int bb) {
        const int* tk = sTok + bb * 32;
        uint32_t xa = sb32 + (OFF_X + bb * XBUF) * 4;
#pragma unroll
        for (int i = 0; i < 4; ++i) {
            int task = tid + i * 256;
            int row = task >> 5, ch = task & 31;
            cp16(xa + row * (XST * 4) + ch * 16, emb + (long)tk[row] * 128 + ch * 4);
        }
        if (HAS_CHILD) {
            uint32_t sa = sb32 + (OFF_S + bb * XBUF) * 4;
#pragma unroll
            for (int i = 0; i < 4; ++i) {
                int task = tid + i * 256;
                int row = task >> 5, ch = task & 31;
                cp16(sa + row * (XST * 4) + ch * 16,
                     hsum_in + (long)(tt * 32 + row) * 128 + ch * 4);
            }
        }
    };
    auto fetch_tok = [&](int tt) -> int {   // call with tid<32
        int gr = tt * 32 + tid;
        int b  = gr >> Lshift;
        return tokens[b * NTOT + tok_start + (gr - (b << Lshift))];
    };

    // Prologue: tokens+issue for first tile; prefetch next tile's tokens.
    int t0 = blockIdx.x;
    int tokreg = 0;
    if (tid < 32) sTok[tid] = fetch_tok(t0);
    __syncthreads();
    issue_tile(t0, 0);
    cp_commit();
    if (tid < 32 && t0 + grid < numTiles) tokreg = fetch_tok(t0 + grid);

    int phase = 0;
    for (int t = t0; t < numTiles; t += grid) {
        const int buf = phase;
        const int nxt = t + grid;
        if (tid < 32 && nxt < numTiles) sTok[(buf ^ 1) * 32 + tid] = tokreg;
        __syncthreads();                       // tokens visible; prior reads of buf^1 done
        if (nxt < numTiles) issue_tile(nxt, buf ^ 1);
        cp_commit();
        if (tid < 32 && nxt + grid < numTiles) tokreg = fetch_tok(nxt + grid);
        cp_wait1();                            // tile t's data landed
        __syncthreads();

        // MMA on buf.
        float acc[4][4];
#pragma unroll
        for (int tt = 0; tt < 4; ++tt)
#pragma unroll
            for (int i = 0; i < 4; ++i) acc[tt][i] = 0.f;

        const uint32_t* Xu = (const uint32_t*)(sm + OFF_X + buf * XBUF);
#pragma unroll 4
        for (int ks = 0; ks < 16; ++ks) {
            const int kk = ks * 8;
            uint32_t a0 = cvtb(Xu[xr0 + kk]);
            uint32_t a1 = cvtb(Xu[xr0 + 8 * XST + kk]);
            uint32_t a2 = cvtb(Xu[xr0 + kk + 4]);
            uint32_t a3 = cvtb(Xu[xr0 + 8 * XST + kk + 4]);
#pragma unroll
            for (int tt = 0; tt < 4; ++tt) {
                uint2 bb = *(const uint2*)&WcU[wb0 + tt * 8 * WST + kk];
                mma_tf32(acc[tt], a0, a1, a2, a3, bb.x, bb.y);
            }
        }
        if (HAS_CHILD) {
            const uint32_t* Su = (const uint32_t*)(sm + OFF_S + buf * XBUF);
#pragma unroll 4
            for (int ks = 0; ks < 16; ++ks) {
                const int kk = ks * 8;
                uint32_t a0 = cvtb(Su[xr0 + kk]);
                uint32_t a1 = cvtb(Su[xr0 + 8 * XST + kk]);
                uint32_t a2 = cvtb(Su[xr0 + kk + 4]);
                uint32_t a3 = cvtb(Su[xr0 + 8 * XST + kk + 4]);
#pragma unroll
                for (int tt = 0; tt < 4; ++tt) {
                    uint2 bb = *(const uint2*)&WsU[wb0 + tt * 8 * WST + kk];
                    mma_tf32(acc[tt], a0, a1, a2, a3, bb.x, bb.y);
                }
            }
        }

        const int rowBase = t * 32;

        // Sibling sums -> hsum_out (quads of node rows; +4*bias).
        {
            const bool writer = (lane & 12) == 0;
            const int bit4 = (lane >> 4) & 1;
#pragma unroll
            for (int half = 0; half < 2; ++half) {
#pragma unroll
                for (int tt = 0; tt < 4; ++tt) {
#pragma unroll
                    for (int j = 0; j < 2; ++j) {
                        float v = acc[tt][half * 2 + j];
                        v += __shfl_xor_sync(0xffffffffu, v, 4);
                        v += __shfl_xor_sync(0xffffffffu, v, 8);
                        if (writer) {
                            int prow = ((rowBase + g * 16) >> 2) + half * 2 + bit4;
                            int col  = cg * 32 + tt * 8 + 2 * c4 + j;
                            hsum_out[(long)prow * 128 + col] = v + 4.f * bias_r[tt][j];
                        }
                    }
                }
            }
        }
        // Relu-max (tile lies inside one batch: L >= 64 here).
#pragma unroll
        for (int tt = 0; tt < 4; ++tt) {
#pragma unroll
            for (int j = 0; j < 2; ++j) {
                float m = fmaxf(acc[tt][j], acc[tt][j + 2]);
                m = fmaxf(m, __shfl_xor_sync(0xffffffffu, m, 4));
                m = fmaxf(m, __shfl_xor_sync(0xffffffffu, m, 8));
                m = fmaxf(m, __shfl_xor_sync(0xffffffffu, m, 16));
                if (lane < 4)
                    sRed[g * 128 + cg * 32 + tt * 8 + 2 * c4 + j] = m + bias_r[tt][j];
            }
        }
        __syncthreads();
        if (tid < 128) {
            float mm = fmaxf(fmaxf(sRed[tid], sRed[128 + tid]), 0.f);
            int b = rowBase >> Lshift;
            atomicMax((int*)&out[(b << 7) + tid], __float_as_int(mm));
        }
        phase ^= 1;
    }
}

// ───────── fused tail: levels d=2,1,0 per batch element ─────────
__global__ __launch_bounds__(256)
void tail_kernel(const int*   __restrict__ tokens,
                 const float* __restrict__ emb,
                 const float* __restrict__ WcW, const float* __restrict__ Wcb,
                 const float* __restrict__ WsW, const float* __restrict__ Wsb,
                 const float* __restrict__ S2,
                 float*       __restrict__ out) {
    extern __shared__ float sm[];
    constexpr int OFF_WS   = 128 * WST;
    constexpr int OFF_X    = OFF_WS + 128 * WST;
    constexpr int OFF_SS   = OFF_X + 21 * XST;
    constexpr int OFF_BIAS = OFF_SS + 16 * XST;
    constexpr int OFF_TOK  = OFF_BIAS + 128;

    float* sX    = sm + OFF_X;
    float* sS    = sm + OFF_SS;
    float* sBias = sm + OFF_BIAS;
    int*   sTok  = (int*)(sm + OFF_TOK);

    const int tid  = threadIdx.x;
    const int lane = tid & 31;
    const int w    = tid >> 5;
    const int g4   = lane >> 2;
    const int c4   = lane & 3;

    for (int i = tid; i < 16384; i += 256) {
        int ch = i >> 7, k = i & 127;
        int d  = ch * WST + (k & ~7) + 2 * (k & 3) + ((k >> 2) & 1);
        sm[d] = __uint_as_float(f2tf32(WcW[i]));
        sm[OFF_WS + d] = __uint_as_float(f2tf32(WsW[i]));
    }
    if (tid < 128) sBias[tid] = Wcb[tid] + 4.f * Wsb[tid];
    __syncthreads();

    float bias_r[2][2];
#pragma unroll
    for (int t = 0; t < 2; ++t)
#pragma unroll
        for (int j = 0; j < 2; ++j)
            bias_r[t][j] = sBias[w * 16 + t * 8 + 2 * c4 + j];

    const uint32_t* WcU = (const uint32_t*)sm;
    const uint32_t* WsU = (const uint32_t*)(sm + OFF_WS);
    const uint32_t* Xu  = (const uint32_t*)sX;
    const uint32_t* Su  = (const uint32_t*)sS;
    const int wb0 = (w * 16 + g4) * WST + 2 * c4;

    auto do_gemm = [&](float (&acc)[2][4], const uint32_t* Au, int baseRow,
                       const uint32_t* WU) {
        const int ar0 = (baseRow + g4) * XST + c4;
#pragma unroll 4
        for (int ks = 0; ks < 16; ++ks) {
            const int kk = ks * 8;
            uint32_t a0 = cvtb(Au[ar0 + kk]);
            uint32_t a1 = cvtb(Au[ar0 + 8 * XST + kk]);
            uint32_t a2 = cvtb(Au[ar0 + kk + 4]);
            uint32_t a3 = cvtb(Au[ar0 + 8 * XST + kk + 4]);
#pragma unroll
            for (int t = 0; t < 2; ++t) {
                uint2 bb = *(const uint2*)&WU[wb0 + t * 8 * WST + kk];
                mma_tf32(acc[t], a0, a1, a2, a3, bb.x, bb.y);
            }
        }
    };

    for (int b = blockIdx.x; b < 512; b += gridDim.x) {
        if (tid < 21) sTok[tid] = tokens[b * NTOT + tid];
        __syncthreads();
        for (int f = tid; f < 21 * 32; f += 256) {
            int row = f >> 5, ch = f & 31;
            *(float4*)&sX[row * XST + ch * 4] =
                *(const float4*)&emb[(long)sTok[row] * 128 + ch * 4];
        }
        for (int f = tid; f < 16 * 32; f += 256) {
            int row = f >> 5, ch = f & 31;
            *(float4*)&sS[row * XST + ch * 4] =
                *(const float4*)&S2[(long)(b * 16 + row) * 128 + ch * 4];
        }
        __syncthreads();

        float mx[2][2] = {{0.f, 0.f}, {0.f, 0.f}};
        const bool writer = (lane & 12) == 0;
        const int bit4 = (lane >> 4) & 1;

        // ── level 2: 16 rows (nodes 5..20), S rows 0..15 ──
        {
            float acc[2][4] = {{0, 0, 0, 0}, {0, 0, 0, 0}};
            do_gemm(acc, Xu, 5, WcU);
            do_gemm(acc, Su, 0, WsU);
            __syncthreads();   // all reads of sS done before overwrite
#pragma unroll
            for (int t = 0; t < 2; ++t)
#pragma unroll
                for (int j = 0; j < 2; ++j)
                    mx[t][j] = fmaxf(mx[t][j],
                        fmaxf(acc[t][j], acc[t][j + 2]) + bias_r[t][j]);
#pragma unroll
            for (int half = 0; half < 2; ++half)
#pragma unroll
                for (int t = 0; t < 2; ++t)
#pragma unroll
                    for (int j = 0; j < 2; ++j) {
                        float v = acc[t][half * 2 + j];
                        v += __shfl_xor_sync(0xffffffffu, v, 4);
                        v += __shfl_xor_sync(0xffffffffu, v, 8);
                        if (writer) {
                            int prow = half * 2 + bit4;   // s1 rows 0..3
                            int col  = w * 16 + t * 8 + 2 * c4 + j;
                            sS[prow * XST + col] = v + 4.f * bias_r[t][j];
                        }
                    }
            __syncthreads();
        }
        // ── level 1: 4 valid rows (nodes 1..4; X base row 1, S rows 0..3) ──
        {
            float acc[2][4] = {{0, 0, 0, 0}, {0, 0, 0, 0}};
            do_gemm(acc, Xu, 1, WcU);
            do_gemm(acc, Su, 0, WsU);
            __syncthreads();
            if (g4 < 4) {
#pragma unroll
                for (int t = 0; t < 2; ++t)
#pragma unroll
                    for (int j = 0; j < 2; ++j)
                        mx[t][j] = fmaxf(mx[t][j], acc[t][j] + bias_r[t][j]);
            }
#pragma unroll
            for (int t = 0; t < 2; ++t)
#pragma unroll
                for (int j = 0; j < 2; ++j) {
                    float v = acc[t][j];                // half 0: rows g4
                    v += __shfl_xor_sync(0xffffffffu, v, 4);
                    v += __shfl_xor_sync(0xffffffffu, v, 8);
                    if (writer && bit4 == 0) {          // lanes 0..3 -> s0 row 0
                        int col = w * 16 + t * 8 + 2 * c4 + j;
                        sS[col] = v + 4.f * bias_r[t][j];
                    }
                }
            __syncthreads();
        }
        // ── level 0: 1 valid row (node 0; X base 0, S row 0) ──
        {
            float acc[2][4] = {{0, 0, 0, 0}, {0, 0, 0, 0}};
            do_gemm(acc, Xu, 0, WcU);
            do_gemm(acc, Su, 0, WsU);
            if (g4 == 0) {
#pragma unroll
                for (int t = 0; t < 2; ++t)
#pragma unroll
                    for (int j = 0; j < 2; ++j)
                        mx[t][j] = fmaxf(mx[t][j], acc[t][j] + bias_r[t][j]);
            }
        }
        // final per-channel max over rows -> atomic
#pragma unroll
        for (int t = 0; t < 2; ++t)
#pragma unroll
            for (int j = 0; j < 2; ++j) {
                float m = mx[t][j];
                m = fmaxf(m, __shfl_xor_sync(0xffffffffu, m, 4));
                m = fmaxf(m, __shfl_xor_sync(0xffffffffu, m, 8));
                m = fmaxf(m, __shfl_xor_sync(0xffffffffu, m, 16));
                if (lane < 4) {
                    int col = w * 16 + t * 8 + 2 * c4 + j;
                    atomicMax((int*)&out[(b << 7) + col],
                              __float_as_int(fmaxf(m, 0.f)));
                }
            }
        __syncthreads();   // before next batch overwrites sX/sS
    }
}

static constexpr size_t SMEM_LEAF32 =
    (size_t)(128 * WST + 2 * XBUF + 128 + 256 + 64 + 8) * 4;
static constexpr size_t SMEM_INT32 =
    (size_t)(2 * 128 * WST + 4 * XBUF + 128 + 256 + 64 + 8) * 4;
static constexpr size_t SMEM_TAIL =
    (size_t)(2 * 128 * WST + 21 * XST + 16 * XST + 128 + 32) * 4;

extern "C" void kernel_launch(void* const* d_in, const int* in_sizes, int n_in,
                              void* d_out, int out_size) {
    const int*   tokens = (const int*)d_in[0];
    const float* emb    = (const float*)d_in[1];
    const float* WcW    = (const float*)d_in[2];
    const float* Wcb    = (const float*)d_in[3];
    const float* WsW    = (const float*)d_in[4];
    const float* Wsb    = (const float*)d_in[5];
    float*       out    = (float*)d_out;

    cudaFuncSetAttribute(enc32<false>,
                         cudaFuncAttributeMaxDynamicSharedMemorySize, SMEM_LEAF32);
    cudaFuncSetAttribute(enc32<true>,
                         cudaFuncAttributeMaxDynamicSharedMemorySize, SMEM_INT32);
    cudaFuncSetAttribute(tail_kernel,
                         cudaFuncAttributeMaxDynamicSharedMemorySize, SMEM_TAIL);

    float* scratch = nullptr;
    cudaGetSymbolAddress((void**)&scratch, g_scratch);
    float* S4 = scratch + OFF_S4;
    float* S3 = scratch + OFF_S3;
    float* S2 = scratch + OFF_S2;

    cudaMemsetAsync(d_out, 0, (size_t)out_size * sizeof(float), 0);

    // d=5 leaves: 524288 rows -> 16384 tiles; 2 CTAs/SM, double-buffered.
    enc32<false><<<296, 256, SMEM_LEAF32>>>(
        tokens, emb, WcW, Wcb, WsW, Wsb, nullptr, S4, out, 10, 341, 16384);
    // d=4: 131072 rows -> 4096 tiles.
    enc32<true><<<148, 256, SMEM_INT32>>>(
        tokens, emb, WcW, Wcb, WsW, Wsb, S4, S3, out, 8, 85, 4096);
    // d=3: 32768 rows -> 1024 tiles.
    enc32<true><<<148, 256, SMEM_INT32>>>(
        tokens, emb, WcW, Wcb, WsW, Wsb, S3, S2, out, 6, 21, 1024);
    // d=2,1,0 fused: one batch subtree per CTA iteration.
    tail_kernel<<<148, 256, SMEM_TAIL>>>(
        tokens, emb, WcW, Wcb, WsW, Wsb, S2, out);
}

// round 5
// speedup vs baseline: 2.8758x; 1.0137x over previous
#include <cuda_runtime.h>
#include <cstdint>

static constexpr int NTOT = 1365;

// scratch (floats)
static constexpr long OFF_S4  = 0;                           // 131072 x 128
static constexpr long OFF_S3  = OFF_S4 + 512L * 256 * 128;   // 32768 x 128
static constexpr long OFF_S2  = OFF_S3 + 512L * 64 * 128;    // 8192 x 128
static constexpr long OFF_S1  = OFF_S2 + 512L * 16 * 128;    // 2048 x 128
static constexpr long OFF_EMB = OFF_S1 + 512L * 4 * 128;     // 50000 x 128 tf32
static constexpr long SCRATCH_TOTAL = OFF_EMB + 50000L * 128;
__device__ float g_scratch[SCRATCH_TOTAL];

__device__ __forceinline__ uint32_t f2tf32(float f) {
    uint32_t r;
    asm("cvt.rna.tf32.f32 %0, %1;" : "=r"(r) : "f"(f));
    return r;
}
__device__ __forceinline__ float tfr(float f) { return __uint_as_float(f2tf32(f)); }
__device__ __forceinline__ uint32_t smem_u32(const void* p) {
    uint32_t a;
    asm("{ .reg .u64 t; cvta.to.shared.u64 t, %1; cvt.u32.u64 %0, t; }" : "=r"(a) : "l"(p));
    return a;
}
__device__ __forceinline__ void cp16(uint32_t dst, const void* src) {
    asm volatile("cp.async.cg.shared.global [%0], [%1], 16;"
                 :: "r"(dst), "l"(__cvta_generic_to_global(src)));
}
__device__ __forceinline__ void cp_commit() {
    asm volatile("cp.async.commit_group;" ::: "memory");
}
__device__ __forceinline__ void cp_wait1() {
    asm volatile("cp.async.wait_group 1;" ::: "memory");
}
__device__ __forceinline__ void mma_tf32(float (&d)[4],
                                         uint32_t a0, uint32_t a1, uint32_t a2, uint32_t a3,
                                         uint32_t b0, uint32_t b1) {
    asm volatile(
        "mma.sync.aligned.m16n8k8.row.col.f32.tf32.tf32.f32 "
        "{%0,%1,%2,%3}, {%4,%5,%6,%7}, {%8,%9}, {%0,%1,%2,%3};"
        : "+f"(d[0]), "+f"(d[1]), "+f"(d[2]), "+f"(d[3])
        : "r"(a0), "r"(a1), "r"(a2), "r"(a3), "r"(b0), "r"(b1));
}

static constexpr int WST  = 136;
static constexpr int XST  = 132;
static constexpr int XBUF = 32 * XST;

// prep: pre-round emb table to tf32 (stored as fp32 bits).
__global__ void prep_emb(const float* __restrict__ emb, float* __restrict__ embT) {
    long i = (long)(blockIdx.x * blockDim.x + threadIdx.x) * 4;
    if (i < 50000L * 128) {
        float4 v = *(const float4*)(emb + i);
        float4 t;
        t.x = tfr(v.x); t.y = tfr(v.y); t.z = tfr(v.z); t.w = tfr(v.w);
        *(float4*)(embT + i) = t;
    }
}

// ───────── leaf kernel: 256 threads, 32-row tiles, 2 CTAs/SM ─────────
__global__ __launch_bounds__(256)
void enc_leaf(const int*   __restrict__ tokens,
              const float* __restrict__ embT,
              const float* __restrict__ WcW, const float* __restrict__ Wcb,
              const float* __restrict__ Wsb,
              float*       __restrict__ hsum_out,
              float*       __restrict__ out,
              int Lshift, int tok_start, int numTiles) {
    extern __shared__ float sm[];
    constexpr int OFF_X    = 128 * WST;
    constexpr int OFF_BIAS = OFF_X + 2 * XBUF;
    constexpr int OFF_RED  = OFF_BIAS + 128;
    constexpr int OFF_TOK  = OFF_RED + 256;

    float* sBias = sm + OFF_BIAS;
    float* sRed  = sm + OFF_RED;
    int*   sTok  = (int*)(sm + OFF_TOK);
    const uint32_t sb32 = smem_u32(sm);

    const int tid  = threadIdx.x;
    const int lane = tid & 31;
    const int wrp  = tid >> 5;
    const int g    = wrp & 1;
    const int cg   = wrp >> 1;
    const int g4   = lane >> 2;
    const int c4   = lane & 3;

    for (int i = tid; i < 16384; i += 256) {
        int ch = i >> 7, k = i & 127;
        sm[ch * WST + (k & ~7) + 2 * (k & 3) + ((k >> 2) & 1)] = tfr(WcW[i]);
    }
    if (tid < 128) sBias[tid] = Wcb[tid];
    __syncthreads();

    float bias_r[4][2];
#pragma unroll
    for (int t = 0; t < 4; ++t)
#pragma unroll
        for (int j = 0; j < 2; ++j)
            bias_r[t][j] = sBias[cg * 32 + t * 8 + 2 * c4 + j];
    const float wsb4[2] = {4.f * Wsb[cg * 32 + 2 * c4], 4.f * Wsb[cg * 32 + 2 * c4 + 1]};
    // note: wsb added per-column below via index t — recompute properly:
    float wsb_r[4][2];
#pragma unroll
    for (int t = 0; t < 4; ++t)
#pragma unroll
        for (int j = 0; j < 2; ++j)
            wsb_r[t][j] = 0.f;   // leaf: hsum gets only 4*child-bias = 4*Wcb (already in bias_r)
    (void)wsb4; (void)wsb_r;

    const uint32_t* WcU = (const uint32_t*)sm;
    const int xr0 = (g * 16 + g4) * XST + c4;
    const int wb0 = (cg * 32 + g4) * WST + 2 * c4;
    const int grid = gridDim.x;

    auto issue_tile = [&](int bb) {
        const int* tk = sTok + bb * 32;
        uint32_t xa = sb32 + (OFF_X + bb * XBUF) * 4;
#pragma unroll
        for (int i = 0; i < 4; ++i) {
            int task = tid + i * 256;
            int row = task >> 5, ch = task & 31;
            cp16(xa + row * (XST * 4) + ch * 16, embT + (long)tk[row] * 128 + ch * 4);
        }
    };
    auto fetch_tok = [&](int tt) -> int {
        int gr = tt * 32 + tid;
        int b  = gr >> Lshift;
        return tokens[b * NTOT + tok_start + (gr - (b << Lshift))];
    };

    int t0 = blockIdx.x;
    int tokreg = 0;
    if (tid < 32) sTok[tid] = fetch_tok(t0);
    __syncthreads();
    issue_tile(0);
    cp_commit();
    if (tid < 32 && t0 + grid < numTiles) tokreg = fetch_tok(t0 + grid);

    int phase = 0;
    for (int t = t0; t < numTiles; t += grid) {
        const int buf = phase;
        const int nxt = t + grid;
        if (tid < 32 && nxt < numTiles) sTok[(buf ^ 1) * 32 + tid] = tokreg;
        __syncthreads();
        if (nxt < numTiles) issue_tile(buf ^ 1);
        cp_commit();
        if (tid < 32 && nxt + grid < numTiles) tokreg = fetch_tok(nxt + grid);
        cp_wait1();
        __syncthreads();

        float acc[4][4];
#pragma unroll
        for (int tt = 0; tt < 4; ++tt)
#pragma unroll
            for (int i = 0; i < 4; ++i) acc[tt][i] = 0.f;

        const uint32_t* Xu = (const uint32_t*)(sm + OFF_X + buf * XBUF);
#pragma unroll 4
        for (int ks = 0; ks < 16; ++ks) {
            const int kk = ks * 8;
            uint32_t a0 = Xu[xr0 + kk];
            uint32_t a1 = Xu[xr0 + 8 * XST + kk];
            uint32_t a2 = Xu[xr0 + kk + 4];
            uint32_t a3 = Xu[xr0 + 8 * XST + kk + 4];
#pragma unroll
            for (int tt = 0; tt < 4; ++tt) {
                uint2 bb = *(const uint2*)&WcU[wb0 + tt * 8 * WST + kk];
                mma_tf32(acc[tt], a0, a1, a2, a3, bb.x, bb.y);
            }
        }

        const int rowBase = t * 32;
        {
            const bool writer = (lane & 12) == 0;
            const int bit4 = (lane >> 4) & 1;
#pragma unroll
            for (int half = 0; half < 2; ++half) {
#pragma unroll
                for (int tt = 0; tt < 4; ++tt) {
#pragma unroll
                    for (int j = 0; j < 2; ++j) {
                        float v = acc[tt][half * 2 + j];
                        v += __shfl_xor_sync(0xffffffffu, v, 4);
                        v += __shfl_xor_sync(0xffffffffu, v, 8);
                        if (writer) {
                            int prow = ((rowBase + g * 16) >> 2) + half * 2 + bit4;
                            int col  = cg * 32 + tt * 8 + 2 * c4 + j;
                            hsum_out[(long)prow * 128 + col] = tfr(v + 4.f * bias_r[tt][j]);
                        }
                    }
                }
            }
        }
#pragma unroll
        for (int tt = 0; tt < 4; ++tt) {
#pragma unroll
            for (int j = 0; j < 2; ++j) {
                float m = fmaxf(acc[tt][j], acc[tt][j + 2]);
                m = fmaxf(m, __shfl_xor_sync(0xffffffffu, m, 4));
                m = fmaxf(m, __shfl_xor_sync(0xffffffffu, m, 8));
                m = fmaxf(m, __shfl_xor_sync(0xffffffffu, m, 16));
                if (lane < 4)
                    sRed[g * 128 + cg * 32 + tt * 8 + 2 * c4 + j] = m + bias_r[tt][j];
            }
        }
        __syncthreads();
        if (tid < 128) {
            float mm = fmaxf(fmaxf(sRed[tid], sRed[128 + tid]), 0.f);
            int b = rowBase >> Lshift;
            atomicMax((int*)&out[(b << 7) + tid], __float_as_int(mm));
        }
        phase ^= 1;
    }
}

// ───────── internal kernel: 512 threads / 16 warps, 32-row tiles ─────────
__global__ __launch_bounds__(512)
void enc_int(const int*   __restrict__ tokens,
             const float* __restrict__ embT,
             const float* __restrict__ WcW, const float* __restrict__ Wcb,
             const float* __restrict__ WsW, const float* __restrict__ Wsb,
             const float* __restrict__ hsum_in,
             float*       __restrict__ hsum_out,
             float*       __restrict__ out,
             int Lshift, int tok_start, int numTiles) {
    extern __shared__ float sm[];
    constexpr int OFF_WS   = 128 * WST;
    constexpr int OFF_X    = 2 * 128 * WST;
    constexpr int OFF_S    = OFF_X + 2 * XBUF;
    constexpr int OFF_BIAS = OFF_S + 2 * XBUF;
    constexpr int OFF_RED  = OFF_BIAS + 128;
    constexpr int OFF_TOK  = OFF_RED + 256;

    float* sBias = sm + OFF_BIAS;
    float* sRed  = sm + OFF_RED;
    int*   sTok  = (int*)(sm + OFF_TOK);
    const uint32_t sb32 = smem_u32(sm);

    const int tid  = threadIdx.x;
    const int lane = tid & 31;
    const int wrp  = tid >> 5;
    const int g    = wrp & 1;
    const int cg   = wrp >> 1;        // 0..7, 16 channels each
    const int g4   = lane >> 2;
    const int c4   = lane & 3;

    for (int i = tid; i < 16384; i += 512) {
        int ch = i >> 7, k = i & 127;
        int d  = ch * WST + (k & ~7) + 2 * (k & 3) + ((k >> 2) & 1);
        sm[d] = tfr(WcW[i]);
        sm[OFF_WS + d] = tfr(WsW[i]);
    }
    if (tid < 128) sBias[tid] = Wcb[tid] + 4.f * Wsb[tid];
    __syncthreads();

    float bias_r[2][2];
#pragma unroll
    for (int t = 0; t < 2; ++t)
#pragma unroll
        for (int j = 0; j < 2; ++j)
            bias_r[t][j] = sBias[cg * 16 + t * 8 + 2 * c4 + j];

    const uint32_t* WcU = (const uint32_t*)sm;
    const uint32_t* WsU = (const uint32_t*)(sm + OFF_WS);
    const int xr0 = (g * 16 + g4) * XST + c4;
    const int wb0 = (cg * 16 + g4) * WST + 2 * c4;
    const int grid = gridDim.x;

    auto issue_tile = [&](int tt, int bb) {
        const int* tk = sTok + bb * 32;
        uint32_t xa = sb32 + (OFF_X + bb * XBUF) * 4;
        uint32_t sa = sb32 + (OFF_S + bb * XBUF) * 4;
#pragma unroll
        for (int i = 0; i < 2; ++i) {
            int task = tid + i * 512;
            int row = task >> 5, ch = task & 31;
            cp16(xa + row * (XST * 4) + ch * 16, embT + (long)tk[row] * 128 + ch * 4);
            cp16(sa + row * (XST * 4) + ch * 16,
                 hsum_in + (long)(tt * 32 + row) * 128 + ch * 4);
        }
    };
    auto fetch_tok = [&](int tt) -> int {
        int gr = tt * 32 + tid;
        int b  = gr >> Lshift;
        return tokens[b * NTOT + tok_start + (gr - (b << Lshift))];
    };

    int t0 = blockIdx.x;
    int tokreg = 0;
    if (tid < 32) sTok[tid] = fetch_tok(t0);
    __syncthreads();
    issue_tile(t0, 0);
    cp_commit();
    if (tid < 32 && t0 + grid < numTiles) tokreg = fetch_tok(t0 + grid);

    int phase = 0;
    for (int t = t0; t < numTiles; t += grid) {
        const int buf = phase;
        const int nxt = t + grid;
        if (tid < 32 && nxt < numTiles) sTok[(buf ^ 1) * 32 + tid] = tokreg;
        __syncthreads();
        if (nxt < numTiles) issue_tile(nxt, buf ^ 1);
        cp_commit();
        if (tid < 32 && nxt + grid < numTiles) tokreg = fetch_tok(nxt + grid);
        cp_wait1();
        __syncthreads();

        float acc[2][4];
#pragma unroll
        for (int tt = 0; tt < 2; ++tt)
#pragma unroll
            for (int i = 0; i < 4; ++i) acc[tt][i] = 0.f;

        const uint32_t* Xu = (const uint32_t*)(sm + OFF_X + buf * XBUF);
        const uint32_t* Su = (const uint32_t*)(sm + OFF_S + buf * XBUF);
#pragma unroll 4
        for (int ks = 0; ks < 16; ++ks) {
            const int kk = ks * 8;
            uint32_t a0 = Xu[xr0 + kk];
            uint32_t a1 = Xu[xr0 + 8 * XST + kk];
            uint32_t a2 = Xu[xr0 + kk + 4];
            uint32_t a3 = Xu[xr0 + 8 * XST + kk + 4];
#pragma unroll
            for (int tt = 0; tt < 2; ++tt) {
                uint2 bb = *(const uint2*)&WcU[wb0 + tt * 8 * WST + kk];
                mma_tf32(acc[tt], a0, a1, a2, a3, bb.x, bb.y);
            }
            uint32_t s0 = Su[xr0 + kk];
            uint32_t s1 = Su[xr0 + 8 * XST + kk];
            uint32_t s2 = Su[xr0 + kk + 4];
            uint32_t s3 = Su[xr0 + 8 * XST + kk + 4];
#pragma unroll
            for (int tt = 0; tt < 2; ++tt) {
                uint2 bb = *(const uint2*)&WsU[wb0 + tt * 8 * WST + kk];
                mma_tf32(acc[tt], s0, s1, s2, s3, bb.x, bb.y);
            }
        }

        const int rowBase = t * 32;
        {
            const bool writer = (lane & 12) == 0;
            const int bit4 = (lane >> 4) & 1;
#pragma unroll
            for (int half = 0; half < 2; ++half) {
#pragma unroll
                for (int tt = 0; tt < 2; ++tt) {
#pragma unroll
                    for (int j = 0; j < 2; ++j) {
                        float v = acc[tt][half * 2 + j];
                        v += __shfl_xor_sync(0xffffffffu, v, 4);
                        v += __shfl_xor_sync(0xffffffffu, v, 8);
                        if (writer) {
                            int prow = ((rowBase + g * 16) >> 2) + half * 2 + bit4;
                            int col  = cg * 16 + tt * 8 + 2 * c4 + j;
                            hsum_out[(long)prow * 128 + col] = tfr(v + 4.f * bias_r[tt][j]);
                        }
                    }
                }
            }
        }
#pragma unroll
        for (int tt = 0; tt < 2; ++tt) {
#pragma unroll
            for (int j = 0; j < 2; ++j) {
                float m = fmaxf(acc[tt][j], acc[tt][j + 2]);
                m = fmaxf(m, __shfl_xor_sync(0xffffffffu, m, 4));
                m = fmaxf(m, __shfl_xor_sync(0xffffffffu, m, 8));
                m = fmaxf(m, __shfl_xor_sync(0xffffffffu, m, 16));
                if (lane < 4)
                    sRed[g * 128 + cg * 16 + tt * 8 + 2 * c4 + j] = m + bias_r[tt][j];
            }
        }
        __syncthreads();
        if (Lshift >= 5) {
            if (tid < 128) {
                float mm = fmaxf(fmaxf(sRed[tid], sRed[128 + tid]), 0.f);
                int b = rowBase >> Lshift;
                atomicMax((int*)&out[(b << 7) + tid], __float_as_int(mm));
            }
        } else {  // Lshift == 4: each 16-row half is one batch element
            if (tid < 256) {
                float mm = fmaxf(sRed[tid], 0.f);
                int b = (rowBase >> 4) + (tid >> 7);
                atomicMax((int*)&out[(b << 7) + (tid & 127)], __float_as_int(mm));
            }
        }
        phase ^= 1;
    }
}

// ───────── tail: levels d=1,0; 4 batches per CTA, one pass ─────────
__global__ __launch_bounds__(256)
void tail_kernel(const int*   __restrict__ tokens,
                 const float* __restrict__ embT,
                 const float* __restrict__ WcW, const float* __restrict__ Wcb,
                 const float* __restrict__ WsW, const float* __restrict__ Wsb,
                 const float* __restrict__ S1,
                 float*       __restrict__ out) {
    extern __shared__ float sm[];
    constexpr int OFF_WS   = 128 * WST;
    constexpr int OFF_X    = 2 * 128 * WST;       // 20 rows
    constexpr int OFF_SS   = OFF_X + 20 * XST;    // 16 rows (S1)
    constexpr int OFF_S0   = OFF_SS + 16 * XST;   // 4 rows
    constexpr int OFF_BIAS = OFF_S0 + 4 * XST;
    constexpr int OFF_MX   = OFF_BIAS + 128;      // 4 x 128
    constexpr int OFF_TOK  = OFF_MX + 512;

    float* sX    = sm + OFF_X;
    float* sS    = sm + OFF_SS;
    float* sS0   = sm + OFF_S0;
    float* sBias = sm + OFF_BIAS;
    float* sMx   = sm + OFF_MX;
    int*   sTok  = (int*)(sm + OFF_TOK);

    const int tid  = threadIdx.x;
    const int lane = tid & 31;
    const int w    = tid >> 5;
    const int g4   = lane >> 2;
    const int c4   = lane & 3;
    const int b0   = blockIdx.x * 4;

    for (int i = tid; i < 16384; i += 256) {
        int ch = i >> 7, k = i & 127;
        int d  = ch * WST + (k & ~7) + 2 * (k & 3) + ((k >> 2) & 1);
        sm[d] = tfr(WcW[i]);
        sm[OFF_WS + d] = tfr(WsW[i]);
    }
    if (tid < 128) sBias[tid] = Wcb[tid] + 4.f * Wsb[tid];
    if (tid < 20) {
        int mb = tid / 5, node = tid - mb * 5;
        sTok[tid] = tokens[(b0 + mb) * NTOT + node];
    }
    __syncthreads();

    for (int f = tid; f < 20 * 32; f += 256) {
        int row = f >> 5, ch = f & 31;
        *(float4*)&sX[row * XST + ch * 4] =
            *(const float4*)&embT[(long)sTok[row] * 128 + ch * 4];
    }
    for (int f = tid; f < 16 * 32; f += 256) {
        int row = f >> 5, ch = f & 31;
        *(float4*)&sS[row * XST + ch * 4] =
            *(const float4*)&S1[(long)(b0 * 4 + row) * 128 + ch * 4];
    }
    __syncthreads();

    float bias_r[2][2];
#pragma unroll
    for (int t = 0; t < 2; ++t)
#pragma unroll
        for (int j = 0; j < 2; ++j)
            bias_r[t][j] = sBias[w * 16 + t * 8 + 2 * c4 + j];

    const uint32_t* WcU = (const uint32_t*)sm;
    const uint32_t* WsU = (const uint32_t*)(sm + OFF_WS);
    const uint32_t* Xu  = (const uint32_t*)sX;
    const uint32_t* Su  = (const uint32_t*)sS;
    const uint32_t* S0u = (const uint32_t*)sS0;
    const int wb0 = (w * 16 + g4) * WST + 2 * c4;
    const bool writer = (lane & 12) == 0;
    const int bit4 = (lane >> 4) & 1;

    // ── level 1: 16 rows (4 batches x nodes 1..4) ──
    {
        const int xlo = ((g4 >> 2) * 5 + 1 + (g4 & 3)) * XST + c4;
        const int xhi = ((2 + (g4 >> 2)) * 5 + 1 + (g4 & 3)) * XST + c4;
        const int slo = g4 * XST + c4;
        const int shi = (g4 + 8) * XST + c4;
        float acc[2][4] = {{0, 0, 0, 0}, {0, 0, 0, 0}};
#pragma unroll 4
        for (int ks = 0; ks < 16; ++ks) {
            const int kk = ks * 8;
            uint32_t a0 = Xu[xlo + kk], a1 = Xu[xhi + kk];
            uint32_t a2 = Xu[xlo + kk + 4], a3 = Xu[xhi + kk + 4];
#pragma unroll
            for (int t = 0; t < 2; ++t) {
                uint2 bb = *(const uint2*)&WcU[wb0 + t * 8 * WST + kk];
                mma_tf32(acc[t], a0, a1, a2, a3, bb.x, bb.y);
            }
            uint32_t s0 = Su[slo + kk], s1 = Su[shi + kk];
            uint32_t s2 = Su[slo + kk + 4], s3 = Su[shi + kk + 4];
#pragma unroll
            for (int t = 0; t < 2; ++t) {
                uint2 bb = *(const uint2*)&WsU[wb0 + t * 8 * WST + kk];
                mma_tf32(acc[t], s0, s1, s2, s3, bb.x, bb.y);
            }
        }
        // quad sums -> sS0 (rounded), quad maxes -> sMx (init write)
#pragma unroll
        for (int half = 0; half < 2; ++half) {
#pragma unroll
            for (int t = 0; t < 2; ++t) {
#pragma unroll
                for (int j = 0; j < 2; ++j) {
                    float v = acc[t][half * 2 + j];
                    float s = v;
                    s += __shfl_xor_sync(0xffffffffu, s, 4);
                    s += __shfl_xor_sync(0xffffffffu, s, 8);
                    float m = v + bias_r[t][j];
                    m = fmaxf(m, __shfl_xor_sync(0xffffffffu, m, 4));
                    m = fmaxf(m, __shfl_xor_sync(0xffffffffu, m, 8));
                    if (writer) {
                        int mb = half * 2 + bit4;
                        int col = w * 16 + t * 8 + 2 * c4 + j;
                        sS0[mb * XST + col] = tfr(s + 4.f * bias_r[t][j]);
                        sMx[mb * 128 + col] = m;
                    }
                }
            }
        }
    }
    __syncthreads();

    // ── level 0: 4 valid rows (node 0 per batch) ──
    {
        const int r = g4 & 3;
        const int xlo = (r * 5) * XST + c4;
        const int slo = r * XST + c4;
        float acc[2][4] = {{0, 0, 0, 0}, {0, 0, 0, 0}};
#pragma unroll 4
        for (int ks = 0; ks < 16; ++ks) {
            const int kk = ks * 8;
            uint32_t a0 = Xu[xlo + kk], a2 = Xu[xlo + kk + 4];
#pragma unroll
            for (int t = 0; t < 2; ++t) {
                uint2 bb = *(const uint2*)&WcU[wb0 + t * 8 * WST + kk];
                mma_tf32(acc[t], a0, a0, a2, a2, bb.x, bb.y);
            }
            uint32_t s0 = S0u[slo + kk], s2 = S0u[slo + kk + 4];
#pragma unroll
            for (int t = 0; t < 2; ++t) {
                uint2 bb = *(const uint2*)&WsU[wb0 + t * 8 * WST + kk];
                mma_tf32(acc[t], s0, s0, s2, s2, bb.x, bb.y);
            }
        }
        if (g4 < 4) {
            int mb = g4;
#pragma unroll
            for (int t = 0; t < 2; ++t)
#pragma unroll
                for (int j = 0; j < 2; ++j) {
                    int col = w * 16 + t * 8 + 2 * c4 + j;
                    float v = acc[t][j] + bias_r[t][j];
                    sMx[mb * 128 + col] = fmaxf(sMx[mb * 128 + col], v);
                }
        }
    }
    __syncthreads();

    for (int i = tid; i < 512; i += 256) {
        int mb = i >> 7, col = i & 127;
        float v = fmaxf(sMx[i], 0.f);
        atomicMax((int*)&out[(b0 + mb) * 128 + col], __float_as_int(v));
    }
}

static constexpr size_t SMEM_LEAF =
    (size_t)(128 * WST + 2 * XBUF + 128 + 256 + 64 + 16) * 4;
static constexpr size_t SMEM_INT =
    (size_t)(2 * 128 * WST + 4 * XBUF + 128 + 256 + 64 + 16) * 4;
static constexpr size_t SMEM_TAIL =
    (size_t)(2 * 128 * WST + 40 * XST + 128 + 512 + 32 + 16) * 4;

extern "C" void kernel_launch(void* const* d_in, const int* in_sizes, int n_in,
                              void* d_out, int out_size) {
    const int*   tokens = (const int*)d_in[0];
    const float* emb    = (const float*)d_in[1];
    const float* WcW    = (const float*)d_in[2];
    const float* Wcb    = (const float*)d_in[3];
    const float* WsW    = (const float*)d_in[4];
    const float* Wsb    = (const float*)d_in[5];
    float*       out    = (float*)d_out;

    cudaFuncSetAttribute(enc_leaf, cudaFuncAttributeMaxDynamicSharedMemorySize, SMEM_LEAF);
    cudaFuncSetAttribute(enc_int,  cudaFuncAttributeMaxDynamicSharedMemorySize, SMEM_INT);
    cudaFuncSetAttribute(tail_kernel, cudaFuncAttributeMaxDynamicSharedMemorySize, SMEM_TAIL);

    float* scratch = nullptr;
    cudaGetSymbolAddress((void**)&scratch, g_scratch);
    float* S4   = scratch + OFF_S4;
    float* S3   = scratch + OFF_S3;
    float* S2   = scratch + OFF_S2;
    float* S1   = scratch + OFF_S1;
    float* embT = scratch + OFF_EMB;

    cudaMemsetAsync(d_out, 0, (size_t)out_size * sizeof(float), 0);
    prep_emb<<<(50000 * 128 / 4 + 255) / 256, 256>>>(emb, embT);

    // d=5 leaves: 16384 tiles, 2 CTAs/SM.
    enc_leaf<<<296, 256, SMEM_LEAF>>>(
        tokens, embT, WcW, Wcb, Wsb, S4, out, 10, 341, 16384);
    // d=4: 4096 tiles.
    enc_int<<<148, 512, SMEM_INT>>>(
        tokens, embT, WcW, Wcb, WsW, Wsb, S4, S3, out, 8, 85, 4096);
    // d=3: 1024 tiles.
    enc_int<<<148, 512, SMEM_INT>>>(
        tokens, embT, WcW, Wcb, WsW, Wsb, S3, S2, out, 6, 21, 1024);
    // d=2: 256 tiles, L=16 (per-half max path).
    enc_int<<<148, 512, SMEM_INT>>>(
        tokens, embT, WcW, Wcb, WsW, Wsb, S2, S1, out, 4, 5, 256);
    // d=1,0 fused tail: 128 CTAs x 4 batches, one pass.
    tail_kernel<<<128, 256, SMEM_TAIL>>>(
        tokens, embT, WcW, Wcb, WsW, Wsb, S1, out);
}